// round 5
// baseline (speedup 1.0000x reference)
#include <cuda_runtime.h>
#include <math.h>

#define N_ENT 100000
#define N_USR 50000
#define N_TOT 150000
#define N_RELS 16
#define DIM 64
#define E_KG 1500000
#define E_CF 1500000
#define LEAKY 0.01f

#define NB_KG 98    // ceil(100000/1024)
#define NB_AIN 147  // ceil(150000/1024)
#define NBF 1563    // ceil(100000/64)

// ---------------- scratch (static device globals; no allocation) ----------------
__device__ float d_PQ[128 * 16];          // Wk @ rel^T  (top 64 rows = P, bottom = Q)
__device__ float d_cr[16];                // Wk_b . rel[r]
__device__ float d_At[(size_t)N_ENT * 16];
__device__ float d_Bt[(size_t)N_ENT * 16];
__device__ int   d_kg_cnt[N_ENT];         // histogram, then scatter cursor
__device__ int   d_kg_rp[N_ENT + 1];
__device__ int   d_csr_t[E_KG];
__device__ float d_csr_a[E_KG];           // leaky logits -> attn (in place)
__device__ int   d_ain_cnt[N_TOT];
__device__ int   d_ain_rp[N_TOT + 1];
__device__ int   d_csr_c[E_CF];
__device__ float d_csr_v[E_CF];
__device__ int   d_spine[512];            // [0..255] kg, [256..] ain
__device__ float d_kgbuf[2][(size_t)N_ENT * DIM];
__device__ float d_xy[2][(size_t)N_TOT * DIM];
__device__ float d_ig[(size_t)N_TOT * DIM];
__device__ float d_sum[(size_t)N_TOT * DIM];

// ---------------- f32x2 packed-FMA helpers (sm_103a) ----------------
__device__ __forceinline__ void fma2(unsigned long long& d, unsigned long long a,
                                     unsigned long long b) {
    asm("fma.rn.f32x2 %0, %1, %2, %0;" : "+l"(d) : "l"(a), "l"(b));
}
__device__ __forceinline__ unsigned long long splat2(float x) {
    unsigned long long r;
    asm("mov.b64 %0, {%1, %1};" : "=l"(r) : "r"(__float_as_uint(x)));
    return r;
}
__device__ __forceinline__ void unpack2(unsigned long long v, float& lo, float& hi) {
    unsigned a, b;
    asm("mov.b64 {%0, %1}, %2;" : "=r"(a), "=r"(b) : "l"(v));
    lo = __uint_as_float(a);
    hi = __uint_as_float(b);
}

// ---------------- setup: zero counts + PQ/cr precompute ----------------
__global__ void k_pre(const float* __restrict__ Wk, const float* __restrict__ Wkb,
                      const float* __restrict__ rel) {
    int i = blockIdx.x * 256 + threadIdx.x;
    if (i < N_TOT) {
        d_ain_cnt[i] = 0;
        if (i < N_ENT) d_kg_cnt[i] = 0;
    }
    int j = i - 150016;  // round_up(N_TOT,256)
    if (j >= 0 && j < 2048) {
        int jj = j >> 4, r = j & 15;
        float s = 0.f;
        #pragma unroll
        for (int d = 0; d < 64; d++) s += Wk[jj * 64 + d] * rel[r * 64 + d];
        d_PQ[jj * 16 + r] = s;
    } else if (j >= 2048 && j < 2064) {
        int r = j - 2048;
        float s = 0.f;
        #pragma unroll
        for (int d = 0; d < 64; d++) s += Wkb[d] * rel[r * 64 + d];
        d_cr[r] = s;
    }
}

// At[n][r] = E0[n] . P[:,r];  Bt[n][r] = E0[n] . Q[:,r]
__global__ void k_atbt(const float* __restrict__ E0) {
    __shared__ float sPQ[128 * 16];
    __shared__ float sE[16][64];
    int tid = threadIdx.x;  // 256
    for (int i = tid; i < 2048; i += 256) sPQ[i] = d_PQ[i];
    int nb = blockIdx.x * 16;
    for (int i = tid; i < 1024; i += 256)
        sE[i >> 6][i & 63] = E0[(size_t)(nb + (i >> 6)) * 64 + (i & 63)];
    __syncthreads();
    int ln = tid >> 4, r = tid & 15;
    float a = 0.f, b = 0.f;
    #pragma unroll
    for (int j = 0; j < 64; j++) {
        float e = sE[ln][j];
        a += e * sPQ[j * 16 + r];
        b += e * sPQ[(64 + j) * 16 + r];
    }
    int n = nb + ln;
    d_At[(size_t)n * 16 + r] = a;
    d_Bt[(size_t)n * 16 + r] = b;
}

// ---------------- CSR build ----------------
__global__ void k_hist(const int* __restrict__ kgh, const int* __restrict__ ar) {
    int e = blockIdx.x * blockDim.x + threadIdx.x;
    if (e < E_KG) {
        atomicAdd(&d_kg_cnt[kgh[e]], 1);
    } else {
        int e2 = e - E_KG;
        if (e2 < E_CF) atomicAdd(&d_ain_cnt[ar[e2]], 1);
    }
}

__global__ void k_scan1() {
    __shared__ int sh[1024];
    int which = blockIdx.x >= NB_KG;
    int b = which ? blockIdx.x - NB_KG : blockIdx.x;
    const int* cnt = which ? d_ain_cnt : d_kg_cnt;
    int* rp = which ? d_ain_rp : d_kg_rp;
    int N = which ? N_TOT : N_ENT;
    int base = which ? 256 : 0;
    int t = threadIdx.x;
    int i = b * 1024 + t;
    sh[t] = (i < N) ? cnt[i] : 0;
    __syncthreads();
    for (int s = 1; s < 1024; s <<= 1) {
        int x = (t >= s) ? sh[t - s] : 0;
        __syncthreads();
        sh[t] += x;
        __syncthreads();
    }
    if (i < N) rp[i + 1] = sh[t];
    if (t == 1023) d_spine[base + b] = sh[1023];
}

__global__ void k_scan2() {
    __shared__ int sh[1024];
    int which = blockIdx.x;  // 0 kg, 1 ain
    int nb = which ? NB_AIN : NB_KG;
    int base = which ? 256 : 0;
    int t = threadIdx.x;
    sh[t] = (t < nb) ? d_spine[base + t] : 0;
    __syncthreads();
    for (int s = 1; s < 1024; s <<= 1) {
        int x = (t >= s) ? sh[t - s] : 0;
        __syncthreads();
        sh[t] += x;
        __syncthreads();
    }
    if (t < nb) d_spine[base + t] = sh[t];
}

// final offset add + initialize scatter cursors (cnt[i] = rp[i])
__global__ void k_scan3c() {
    int which = blockIdx.x >= NB_KG;
    int b = which ? blockIdx.x - NB_KG : blockIdx.x;
    int* rp = which ? d_ain_rp : d_kg_rp;
    int* cnt = which ? d_ain_cnt : d_kg_cnt;
    int N = which ? N_TOT : N_ENT;
    int base = which ? 256 : 0;
    int i = b * 1024 + threadIdx.x;
    int off = (b > 0) ? d_spine[base + b - 1] : 0;
    if (i < N) {
        int v = rp[i + 1] + off;
        rp[i + 1] = v;
        if (i + 1 < N) cnt[i + 1] = v;
    }
    if (b == 0 && threadIdx.x == 0) {
        rp[0] = 0;
        cnt[0] = 0;
    }
}

// merged scatter (kg edges with logit computation; ain edges plain)
__global__ void k_scatter(const int* __restrict__ h, const int* __restrict__ t,
                          const int* __restrict__ r, const int* __restrict__ ar,
                          const int* __restrict__ ac, const float* __restrict__ av) {
    int e = blockIdx.x * blockDim.x + threadIdx.x;
    if (e < E_KG) {
        int hh = h[e], tt = t[e], rr = r[e];
        int p = atomicAdd(&d_kg_cnt[hh], 1);
        float l = d_At[(size_t)tt * 16 + rr] + d_Bt[(size_t)hh * 16 + rr] + d_cr[rr];
        l = (l >= 0.f) ? l : LEAKY * l;
        d_csr_t[p] = tt;
        d_csr_a[p] = l;
    } else {
        int e2 = e - E_KG;
        if (e2 >= E_CF) return;
        int p = atomicAdd(&d_ain_cnt[ar[e2]], 1);
        d_csr_c[p] = ac[e2];
        d_csr_v[p] = av[e2];
    }
}

// per-row softmax (warp per row), in place
__global__ void k_softmax() {
    int w = (blockIdx.x * blockDim.x + threadIdx.x) >> 5;
    int lane = threadIdx.x & 31;
    if (w >= N_ENT) return;
    int s = d_kg_rp[w], e = d_kg_rp[w + 1];
    if (s == e) return;
    float m = -1e30f;
    for (int i = s + lane; i < e; i += 32) m = fmaxf(m, d_csr_a[i]);
    #pragma unroll
    for (int o = 16; o; o >>= 1) m = fmaxf(m, __shfl_xor_sync(~0u, m, o));
    float sum = 0.f;
    for (int i = s + lane; i < e; i += 32) {
        float ex = __expf(d_csr_a[i] - m);
        d_csr_a[i] = ex;
        sum += ex;
    }
    #pragma unroll
    for (int o = 16; o; o >>= 1) sum += __shfl_xor_sync(~0u, sum, o);
    float inv = 1.f / sum;
    for (int i = s + lane; i < e; i += 32) d_csr_a[i] *= inv;
}

// ---------------- init copies ----------------
__global__ void k_init(const float* __restrict__ E0) {
    int i = blockIdx.x * blockDim.x + threadIdx.x;
    if (i >= N_TOT * 16) return;
    float4 v = ((const float4*)E0)[i];
    ((float4*)d_xy[0])[i] = v;
    ((float4*)d_sum)[i] = v;
    if (i < N_ENT * 16) ((float4*)d_kgbuf[0])[i] = v;
}

// ---------------- merged SpMM (kg rows then ain rows), shuffle-staged edges ----------------
__global__ void k_spmm(int cur) {
    int gw = (blockIdx.x * blockDim.x + threadIdx.x) >> 5;
    int lane = threadIdx.x & 31;
    const float* __restrict__ X;
    float* Y;
    const int* __restrict__ ci;
    const float* __restrict__ cv;
    int s, e;
    size_t row;
    if (gw < N_ENT) {
        X = d_kgbuf[cur]; Y = d_kgbuf[cur ^ 1];
        s = d_kg_rp[gw]; e = d_kg_rp[gw + 1];
        ci = d_csr_t; cv = d_csr_a; row = gw;
    } else {
        int w = gw - N_ENT;
        X = d_xy[cur]; Y = d_ig;
        s = d_ain_rp[w]; e = d_ain_rp[w + 1];
        ci = d_csr_c; cv = d_csr_v; row = w;
    }
    float ax = 0.f, ay = 0.f;
    const float* Xl = X + lane * 2;
    for (int base = s; base < e; base += 32) {
        int idx = base + lane;
        int t = 0;
        float a = 0.f;
        if (idx < e) { t = ci[idx]; a = cv[idx]; }
        int n = min(32, e - base);
        int j = 0;
        for (; j + 4 <= n; j += 4) {
            int c0 = __shfl_sync(~0u, t, j + 0), c1 = __shfl_sync(~0u, t, j + 1);
            int c2 = __shfl_sync(~0u, t, j + 2), c3 = __shfl_sync(~0u, t, j + 3);
            float a0 = __shfl_sync(~0u, a, j + 0), a1 = __shfl_sync(~0u, a, j + 1);
            float a2 = __shfl_sync(~0u, a, j + 2), a3 = __shfl_sync(~0u, a, j + 3);
            float2 x0 = *(const float2*)(Xl + (size_t)c0 * 64);
            float2 x1 = *(const float2*)(Xl + (size_t)c1 * 64);
            float2 x2 = *(const float2*)(Xl + (size_t)c2 * 64);
            float2 x3 = *(const float2*)(Xl + (size_t)c3 * 64);
            ax += a0 * x0.x + a1 * x1.x + a2 * x2.x + a3 * x3.x;
            ay += a0 * x0.y + a1 * x1.y + a2 * x2.y + a3 * x3.y;
        }
        for (; j < n; j++) {
            int c = __shfl_sync(~0u, t, j);
            float av = __shfl_sync(~0u, a, j);
            float2 x = *(const float2*)(Xl + (size_t)c * 64);
            ax += av * x.x;
            ay += av * x.y;
        }
    }
    *(float2*)(Y + row * 64 + lane * 2) = make_float2(ax, ay);
}

// ---------------- fusion gate (items) + pass-through (users), f32x2 FMAs ----------------
__global__ void k_fusion_users(const float* __restrict__ Wa, const float* __restrict__ Wb,
                               int cur) {
    if (blockIdx.x >= NBF) {
        // users: pass through + accumulate
        int i = (blockIdx.x - NBF) * 256 + threadIdx.x;
        if (i >= N_USR * 16) return;
        const float4* src = (const float4*)(d_ig + (size_t)N_ENT * 64);
        float4 v = src[i];
        ((float4*)(d_xy[cur ^ 1] + (size_t)N_ENT * 64))[i] = v;
        float4* as = (float4*)(d_sum + (size_t)N_ENT * 64);
        float4 a = as[i];
        a.x += v.x; a.y += v.y; a.z += v.z; a.w += v.w;
        as[i] = a;
        return;
    }
    __shared__ float sKG[64][68];
    __shared__ float sIG[64][68];
    const float* __restrict__ KG = d_kgbuf[cur ^ 1];
    const float* __restrict__ IG = d_ig;
    float* XY = d_xy[cur ^ 1];
    int row0 = blockIdx.x * 64;
    int tid = threadIdx.x;  // 256
    for (int i = tid; i < 1024; i += 256) {
        int r = i >> 4, c4 = (i & 15) * 4;
        int gr = row0 + r;
        float4 kgv = make_float4(0.f, 0.f, 0.f, 0.f), igv = kgv;
        if (gr < N_ENT) {
            kgv = *(const float4*)(KG + (size_t)gr * 64 + c4);
            igv = *(const float4*)(IG + (size_t)gr * 64 + c4);
        }
        *(float4*)&sKG[r][c4] = kgv;
        *(float4*)&sIG[r][c4] = igv;
    }
    __syncthreads();
    int tx = tid & 15, ty = tid >> 4;
    // acc[i][p] holds output cols (tx*4 + 2p, tx*4 + 2p + 1) for row ty*4+i
    unsigned long long acc[4][2];
    #pragma unroll
    for (int i = 0; i < 4; i++) { acc[i][0] = 0ull; acc[i][1] = 0ull; }
    const float4* WaP = (const float4*)(Wa + tx * 4);
    const float4* WbP = (const float4*)(Wb + tx * 4);
    #pragma unroll
    for (int k4 = 0; k4 < 64; k4 += 4) {
        float4 kg[4], ig[4];
        #pragma unroll
        for (int i = 0; i < 4; i++) {
            kg[i] = *(const float4*)&sKG[ty * 4 + i][k4];
            ig[i] = *(const float4*)&sIG[ty * 4 + i][k4];
        }
        #pragma unroll
        for (int kk = 0; kk < 4; kk++) {
            float4 wav = WaP[(k4 + kk) * 16];
            float4 wbv = WbP[(k4 + kk) * 16];
            unsigned long long wa0, wa1, wb0, wb1;
            asm("mov.b64 %0, {%1, %2};" : "=l"(wa0) : "f"(wav.x), "f"(wav.y));
            asm("mov.b64 %0, {%1, %2};" : "=l"(wa1) : "f"(wav.z), "f"(wav.w));
            asm("mov.b64 %0, {%1, %2};" : "=l"(wb0) : "f"(wbv.x), "f"(wbv.y));
            asm("mov.b64 %0, {%1, %2};" : "=l"(wb1) : "f"(wbv.z), "f"(wbv.w));
            #pragma unroll
            for (int i = 0; i < 4; i++) {
                float kgs = ((const float*)&kg[i])[kk];
                float igs = ((const float*)&ig[i])[kk];
                unsigned long long ks = splat2(kgs);
                unsigned long long is2 = splat2(igs);
                fma2(acc[i][0], ks, wa0);
                fma2(acc[i][1], ks, wa1);
                fma2(acc[i][0], is2, wb0);
                fma2(acc[i][1], is2, wb1);
            }
        }
    }
    #pragma unroll
    for (int i = 0; i < 4; i++) {
        int gr = row0 + ty * 4 + i;
        if (gr >= N_ENT) break;
        float4 kgv = *(const float4*)&sKG[ty * 4 + i][tx * 4];
        float4 igv = *(const float4*)&sIG[ty * 4 + i][tx * 4];
        float s0, s1, s2, s3;
        unpack2(acc[i][0], s0, s1);
        unpack2(acc[i][1], s2, s3);
        float4 o;
        float g;
        g = 1.f / (1.f + __expf(-s0)); o.x = g * kgv.x + (1.f - g) * igv.x;
        g = 1.f / (1.f + __expf(-s1)); o.y = g * kgv.y + (1.f - g) * igv.y;
        g = 1.f / (1.f + __expf(-s2)); o.z = g * kgv.z + (1.f - g) * igv.z;
        g = 1.f / (1.f + __expf(-s3)); o.w = g * kgv.w + (1.f - g) * igv.w;
        *(float4*)(XY + (size_t)gr * 64 + tx * 4) = o;
        float4* as = (float4*)(d_sum + (size_t)gr * 64 + tx * 4);
        float4 a = *as;
        a.x += igv.x; a.y += igv.y; a.z += igv.z; a.w += igv.w;
        *as = a;
    }
}

// ---------------- final score GEMM ----------------
__global__ void k_final(const int* __restrict__ uids, const int* __restrict__ iids,
                        float* __restrict__ out) {
    __shared__ float sU[16][68];
    __shared__ float sI[16][68];
    int tx = threadIdx.x, ty = threadIdx.y;
    int u0 = blockIdx.y * 16, i0 = blockIdx.x * 16;
    {
        int ur = uids[u0 + ty];
        *(float4*)&sU[ty][tx * 4] = *(const float4*)(d_sum + (size_t)ur * 64 + tx * 4);
        int ir = iids[i0 + ty];
        *(float4*)&sI[ty][tx * 4] = *(const float4*)(d_sum + (size_t)ir * 64 + tx * 4);
    }
    __syncthreads();
    float acc = 0.f;
    #pragma unroll
    for (int k = 0; k < 64; k++) acc += sU[ty][k] * sI[tx][k];
    out[(size_t)(u0 + ty) * 2048 + i0 + tx] = acc;
}

// ---------------- launch ----------------
extern "C" void kernel_launch(void* const* d_in, const int* in_sizes, int n_in,
                              void* d_out, int out_size) {
    const float* E0   = (const float*)d_in[0];
    const float* rel  = (const float*)d_in[1];
    const float* Wk   = (const float*)d_in[2];
    const float* Wkb  = (const float*)d_in[3];
    const float* Wa   = (const float*)d_in[4];
    const float* Wb   = (const float*)d_in[5];
    const int*   kg_h = (const int*)d_in[6];
    const int*   kg_t = (const int*)d_in[7];
    const int*   kg_r = (const int*)d_in[8];
    const int*   a_r  = (const int*)d_in[9];
    const int*   a_c  = (const int*)d_in[10];
    const float* a_v  = (const float*)d_in[11];
    const int*   uids = (const int*)d_in[12];
    const int*   iids = (const int*)d_in[13];
    float* out = (float*)d_out;

    const int EB = (E_KG + 255) / 256;  // 5860

    k_pre<<<150016 / 256 + 9, 256>>>(Wk, Wkb, rel);
    k_atbt<<<N_ENT / 16, 256>>>(E0);

    k_hist<<<2 * EB, 256>>>(kg_h, a_r);
    k_scan1<<<NB_KG + NB_AIN, 1024>>>();
    k_scan2<<<2, 1024>>>();
    k_scan3c<<<NB_KG + NB_AIN, 1024>>>();
    k_scatter<<<2 * EB, 256>>>(kg_h, kg_t, kg_r, a_r, a_c, a_v);
    k_softmax<<<(N_ENT + 7) / 8, 256>>>();

    k_init<<<(N_TOT * 16 + 255) / 256, 256>>>(E0);

    int cur = 0;
    for (int l = 0; l < 3; l++) {
        k_spmm<<<(N_ENT + N_TOT) / 8, 256>>>(cur);
        k_fusion_users<<<NBF + (N_USR * 16 + 255) / 256, 256>>>(Wa, Wb, cur);
        cur ^= 1;
    }

    dim3 fg(2048 / 16, 1024 / 16), fb(16, 16);
    k_final<<<fg, fb>>>(uids, iids, out);
    (void)in_sizes; (void)n_in; (void)out_size;
}

// round 7
// speedup vs baseline: 1.0853x; 1.0853x over previous
#include <cuda_runtime.h>
#include <math.h>

#define N_ENT 100000
#define N_USR 50000
#define N_TOT 150000
#define DIM 64
#define E_KG 1500000
#define E_CF 1500000
#define LEAKY 0.01f

#define NB_KG 98    // ceil(100000/1024)
#define NB_AIN 147  // ceil(150000/1024)
#define NBF 1563    // ceil(100000/64)

// k_setup block ranges (256 threads)
#define B_H 11719   // ceil(3,000,000/256) edge hist
#define B_I 9375    // N_TOT*16/256 init float4
#define B_P 9       // PQ + cr
#define B_Z 393     // rowsum + spine zero
// k_atbt_scan (1024 threads)
#define B_ATBT 1563 // ceil(100000/64)

// ---------------- scratch (static device globals; zero-initialized at load) ----------------
__device__ float d_PQ[128 * 16];
__device__ float d_cr[16];
__device__ float d_At[(size_t)N_ENT * 16];
__device__ float d_Bt[(size_t)N_ENT * 16];
__device__ int   d_kg_cnt[N_ENT];          // histogram -> cursor (re-zeroed at end of replay)
__device__ int   d_kg_rp[N_ENT + 1];
__device__ int   d_csr_t[E_KG];
__device__ float d_csr_a[E_KG];            // exp(leaky(logit)), unnormalized
__device__ float d_rowsum[N_ENT];
__device__ int   d_ain_cnt[N_TOT];
__device__ int   d_ain_rp[N_TOT + 1];
__device__ int   d_csr_c[E_CF];
__device__ float d_csr_v[E_CF];
__device__ unsigned d_spine[512];          // lookback flags: [0..97] kg, [256..402] ain
__device__ float d_kgbuf[2][(size_t)N_ENT * DIM];
__device__ float d_xy[2][(size_t)N_TOT * DIM];
__device__ float d_ig[(size_t)N_TOT * DIM];
__device__ float d_sum[(size_t)N_TOT * DIM];

// ---------------- f32x2 packed-FMA helpers (sm_103a) ----------------
__device__ __forceinline__ void fma2(unsigned long long& d, unsigned long long a,
                                     unsigned long long b) {
    asm("fma.rn.f32x2 %0, %1, %2, %0;" : "+l"(d) : "l"(a), "l"(b));
}
__device__ __forceinline__ unsigned long long splat2(float x) {
    unsigned long long r;
    asm("mov.b64 %0, {%1, %1};" : "=l"(r) : "r"(__float_as_uint(x)));
    return r;
}
__device__ __forceinline__ void unpack2(unsigned long long v, float& lo, float& hi) {
    unsigned a, b;
    asm("mov.b64 {%0, %1}, %2;" : "=r"(a), "=r"(b) : "l"(v));
    lo = __uint_as_float(a);
    hi = __uint_as_float(b);
}

// ================= Launch 0: hist + init copies + PQ/cr + zero rowsum/spine ===============
__global__ void k_setup(const float* __restrict__ E0, const float* __restrict__ Wk,
                        const float* __restrict__ Wkb, const float* __restrict__ rel,
                        const int* __restrict__ kgh, const int* __restrict__ ar) {
    int b = blockIdx.x, tid = threadIdx.x;
    if (b < B_H) {
        int e = b * 256 + tid;
        if (e < E_KG) {
            atomicAdd(&d_kg_cnt[kgh[e]], 1);
        } else {
            e -= E_KG;
            if (e < E_CF) atomicAdd(&d_ain_cnt[ar[e]], 1);
        }
    } else if (b < B_H + B_I) {
        int i = (b - B_H) * 256 + tid;   // exactly N_TOT*16 float4s
        float4 v = ((const float4*)E0)[i];
        ((float4*)d_xy[0])[i] = v;
        ((float4*)d_sum)[i] = v;
        if (i < N_ENT * 16) ((float4*)d_kgbuf[0])[i] = v;
    } else if (b < B_H + B_I + B_P) {
        int j = (b - B_H - B_I) * 256 + tid;
        if (j < 2048) {
            int jj = j >> 4, r = j & 15;
            float s = 0.f;
            #pragma unroll
            for (int d = 0; d < 64; d++) s += Wk[jj * 64 + d] * rel[r * 64 + d];
            d_PQ[jj * 16 + r] = s;
        } else if (j < 2064) {
            int r = j - 2048;
            float s = 0.f;
            #pragma unroll
            for (int d = 0; d < 64; d++) s += Wkb[d] * rel[r * 64 + d];
            d_cr[r] = s;
        }
    } else {
        int i = (b - B_H - B_I - B_P) * 256 + tid;
        if (i < N_ENT) d_rowsum[i] = 0.f;
        else {
            i -= N_ENT;
            if (i < 512) d_spine[i] = 0u;
        }
    }
}

// ================= Launch 1: At/Bt precompute + single-pass lookback scans ================
__global__ void __launch_bounds__(1024) k_atbt_scan(const float* __restrict__ E0) {
    __shared__ float sm[6144];  // atbt: sPQ[2048] + sE[4096]; scan: reuse as int[1024]
    int t = threadIdx.x;
    if (blockIdx.x < B_ATBT) {
        float* sPQ = sm;
        float* sE = sm + 2048;
        int nb = blockIdx.x * 64;
        for (int i = t; i < 2048; i += 1024) sPQ[i] = d_PQ[i];
        for (int i = t; i < 4096; i += 1024) {
            int rr = nb + (i >> 6);
            sE[i] = (rr < N_ENT) ? E0[(size_t)rr * 64 + (i & 63)] : 0.f;
        }
        __syncthreads();
        int ln = t >> 4, r = t & 15;
        float a = 0.f, bb = 0.f;
        #pragma unroll
        for (int j = 0; j < 64; j++) {
            float e = sE[ln * 64 + j];
            a += e * sPQ[j * 16 + r];
            bb += e * sPQ[(64 + j) * 16 + r];
        }
        int n = nb + ln;
        if (n < N_ENT) {
            d_At[(size_t)n * 16 + r] = a;
            d_Bt[(size_t)n * 16 + r] = bb;
        }
        return;
    }
    // ---- decoupled-lookback scan over both count arrays ----
    int b2 = blockIdx.x - B_ATBT;
    int which = (b2 >= NB_KG);
    int b = which ? b2 - NB_KG : b2;
    int* cnt = which ? d_ain_cnt : d_kg_cnt;
    int* rp = which ? d_ain_rp : d_kg_rp;
    int N = which ? N_TOT : N_ENT;
    int base = which ? 256 : 0;
    int* sh = (int*)sm;
    int i = b * 1024 + t;
    int v = (i < N) ? cnt[i] : 0;
    sh[t] = v;
    __syncthreads();
    for (int s = 1; s < 1024; s <<= 1) {
        int x = (t >= s) ? sh[t - s] : 0;
        __syncthreads();
        sh[t] += x;
        __syncthreads();
    }
    int agg = sh[1023];
    __shared__ int s_ex;
    if (t == 0) {
        volatile unsigned* sp = d_spine;
        if (b == 0) {
            __threadfence();
            sp[base] = (2u << 30) | (unsigned)agg;
            s_ex = 0;
        } else {
            __threadfence();
            sp[base + b] = (1u << 30) | (unsigned)agg;
            int ex = 0;
            int p = b - 1;
            while (true) {
                unsigned w;
                do { w = sp[base + p]; } while ((w >> 30) == 0u);
                ex += (int)(w & 0x3FFFFFFFu);
                if ((w >> 30) == 2u) break;
                p--;
            }
            __threadfence();
            sp[base + b] = (2u << 30) | (unsigned)(ex + agg);
            s_ex = ex;
        }
    }
    __syncthreads();
    int ex = s_ex;
    if (i < N) {
        rp[i + 1] = ex + sh[t];
        cnt[i] = ex + sh[t] - v;   // exclusive prefix -> scatter cursor
    }
    if (b == 0 && t == 0) rp[0] = 0;
}

// ========== Launch 2: merged scatter (kg with inline logit+exp+rowsum; ain plain) ==========
__global__ void k_scatter(const int* __restrict__ h, const int* __restrict__ tt_,
                          const int* __restrict__ r, const int* __restrict__ ar,
                          const int* __restrict__ ac, const float* __restrict__ av) {
    int e = blockIdx.x * blockDim.x + threadIdx.x;
    if (e < E_KG) {
        int hh = h[e], tt = tt_[e], rr = r[e];
        float l = d_At[(size_t)tt * 16 + rr] + d_Bt[(size_t)hh * 16 + rr] + d_cr[rr];
        l = (l >= 0.f) ? l : LEAKY * l;
        float ex = __expf(l);      // logits ~ N(0, 1/8): no max-subtraction needed
        atomicAdd(&d_rowsum[hh], ex);
        int p = atomicAdd(&d_kg_cnt[hh], 1);
        d_csr_t[p] = tt;
        d_csr_a[p] = ex;
    } else {
        int e2 = e - E_KG;
        if (e2 >= E_CF) return;
        int p = atomicAdd(&d_ain_cnt[ar[e2]], 1);
        d_csr_c[p] = ac[e2];
        d_csr_v[p] = av[e2];
    }
}

// ================= Launches 3,5,7: merged SpMM (kg rows then ain rows) =====================
__global__ void __launch_bounds__(256) k_spmm(int cur) {
    int gw = (blockIdx.x * blockDim.x + threadIdx.x) >> 5;
    int lane = threadIdx.x & 31;
    const float* __restrict__ X;
    float* Y;
    const int* __restrict__ ci;
    const float* __restrict__ cv;
    int s, e;
    size_t row;
    bool iskg = (gw < N_ENT);
    if (iskg) {
        X = d_kgbuf[cur]; Y = d_kgbuf[cur ^ 1];
        s = d_kg_rp[gw]; e = d_kg_rp[gw + 1];
        ci = d_csr_t; cv = d_csr_a; row = gw;
    } else {
        int w = gw - N_ENT;
        X = d_xy[cur]; Y = d_ig;
        s = d_ain_rp[w]; e = d_ain_rp[w + 1];
        ci = d_csr_c; cv = d_csr_v; row = w;
    }
    float ax = 0.f, ay = 0.f;
    const float* Xl = X + lane * 2;
    for (int base = s; base < e; base += 32) {
        int idx = base + lane;
        int t = 0;
        float a = 0.f;
        if (idx < e) { t = ci[idx]; a = cv[idx]; }
        int n = e - base; if (n > 32) n = 32;
        int nr = (n + 3) & ~3;        // pad to 4: padded lanes carry a=0 -> contribute 0
        for (int j = 0; j < nr; j += 4) {
            int c0 = __shfl_sync(~0u, t, j + 0), c1 = __shfl_sync(~0u, t, j + 1);
            int c2 = __shfl_sync(~0u, t, j + 2), c3 = __shfl_sync(~0u, t, j + 3);
            float a0 = __shfl_sync(~0u, a, j + 0), a1 = __shfl_sync(~0u, a, j + 1);
            float a2 = __shfl_sync(~0u, a, j + 2), a3 = __shfl_sync(~0u, a, j + 3);
            float2 x0 = *(const float2*)(Xl + (size_t)c0 * 64);
            float2 x1 = *(const float2*)(Xl + (size_t)c1 * 64);
            float2 x2 = *(const float2*)(Xl + (size_t)c2 * 64);
            float2 x3 = *(const float2*)(Xl + (size_t)c3 * 64);
            ax += a0 * x0.x + a1 * x1.x + a2 * x2.x + a3 * x3.x;
            ay += a0 * x0.y + a1 * x1.y + a2 * x2.y + a3 * x3.y;
        }
    }
    float sc = 1.f;
    if (iskg) sc = (e > s) ? 1.f / d_rowsum[row] : 0.f;   // fold softmax normalization
    *(float2*)(Y + row * 64 + lane * 2) = make_float2(ax * sc, ay * sc);
}

// ============ Launches 4,6,8: fusion gate (items, f32x2) + user pass-through ==============
__global__ void k_fusion_users(const float* __restrict__ Wa, const float* __restrict__ Wb,
                               int cur) {
    if (blockIdx.x >= NBF) {
        int i = (blockIdx.x - NBF) * 256 + threadIdx.x;
        if (i >= N_USR * 16) return;
        const float4* src = (const float4*)(d_ig + (size_t)N_ENT * 64);
        float4 v = src[i];
        ((float4*)(d_xy[cur ^ 1] + (size_t)N_ENT * 64))[i] = v;
        float4* as = (float4*)(d_sum + (size_t)N_ENT * 64);
        float4 a = as[i];
        a.x += v.x; a.y += v.y; a.z += v.z; a.w += v.w;
        as[i] = a;
        return;
    }
    __shared__ float sKG[64][68];
    __shared__ float sIG[64][68];
    const float* __restrict__ KG = d_kgbuf[cur ^ 1];
    const float* __restrict__ IG = d_ig;
    float* XY = d_xy[cur ^ 1];
    int row0 = blockIdx.x * 64;
    int tid = threadIdx.x;  // 256
    for (int i = tid; i < 1024; i += 256) {
        int r = i >> 4, c4 = (i & 15) * 4;
        int gr = row0 + r;
        float4 kgv = make_float4(0.f, 0.f, 0.f, 0.f), igv = kgv;
        if (gr < N_ENT) {
            kgv = *(const float4*)(KG + (size_t)gr * 64 + c4);
            igv = *(const float4*)(IG + (size_t)gr * 64 + c4);
        }
        *(float4*)&sKG[r][c4] = kgv;
        *(float4*)&sIG[r][c4] = igv;
    }
    __syncthreads();
    int tx = tid & 15, ty = tid >> 4;
    unsigned long long acc[4][2];
    #pragma unroll
    for (int i = 0; i < 4; i++) { acc[i][0] = 0ull; acc[i][1] = 0ull; }
    const float4* WaP = (const float4*)(Wa + tx * 4);
    const float4* WbP = (const float4*)(Wb + tx * 4);
    #pragma unroll
    for (int k4 = 0; k4 < 64; k4 += 4) {
        float4 kg[4], ig[4];
        #pragma unroll
        for (int i = 0; i < 4; i++) {
            kg[i] = *(const float4*)&sKG[ty * 4 + i][k4];
            ig[i] = *(const float4*)&sIG[ty * 4 + i][k4];
        }
        #pragma unroll
        for (int kk = 0; kk < 4; kk++) {
            float4 wav = WaP[(k4 + kk) * 16];
            float4 wbv = WbP[(k4 + kk) * 16];
            unsigned long long wa0, wa1, wb0, wb1;
            asm("mov.b64 %0, {%1, %2};" : "=l"(wa0) : "f"(wav.x), "f"(wav.y));
            asm("mov.b64 %0, {%1, %2};" : "=l"(wa1) : "f"(wav.z), "f"(wav.w));
            asm("mov.b64 %0, {%1, %2};" : "=l"(wb0) : "f"(wbv.x), "f"(wbv.y));
            asm("mov.b64 %0, {%1, %2};" : "=l"(wb1) : "f"(wbv.z), "f"(wbv.w));
            #pragma unroll
            for (int i = 0; i < 4; i++) {
                unsigned long long ks = splat2(((const float*)&kg[i])[kk]);
                unsigned long long is2 = splat2(((const float*)&ig[i])[kk]);
                fma2(acc[i][0], ks, wa0);
                fma2(acc[i][1], ks, wa1);
                fma2(acc[i][0], is2, wb0);
                fma2(acc[i][1], is2, wb1);
            }
        }
    }
    #pragma unroll
    for (int i = 0; i < 4; i++) {
        int gr = row0 + ty * 4 + i;
        if (gr >= N_ENT) break;
        float4 kgv = *(const float4*)&sKG[ty * 4 + i][tx * 4];
        float4 igv = *(const float4*)&sIG[ty * 4 + i][tx * 4];
        float s0, s1, s2, s3;
        unpack2(acc[i][0], s0, s1);
        unpack2(acc[i][1], s2, s3);
        float4 o;
        float g;
        g = 1.f / (1.f + __expf(-s0)); o.x = g * kgv.x + (1.f - g) * igv.x;
        g = 1.f / (1.f + __expf(-s1)); o.y = g * kgv.y + (1.f - g) * igv.y;
        g = 1.f / (1.f + __expf(-s2)); o.z = g * kgv.z + (1.f - g) * igv.z;
        g = 1.f / (1.f + __expf(-s3)); o.w = g * kgv.w + (1.f - g) * igv.w;
        *(float4*)(XY + (size_t)gr * 64 + tx * 4) = o;
        float4* as = (float4*)(d_sum + (size_t)gr * 64 + tx * 4);
        float4 a = *as;
        a.x += igv.x; a.y += igv.y; a.z += igv.z; a.w += igv.w;
        *as = a;
    }
}

// ====== Launch 9: final score GEMM + re-zero counters for the next graph replay ==========
__global__ void k_final(const int* __restrict__ uids, const int* __restrict__ iids,
                        float* __restrict__ out) {
    int bid = blockIdx.x;
    int tx = threadIdx.x, ty = threadIdx.y;
    if (bid >= 8192) {
        int t = ty * 16 + tx;
        int i = (bid - 8192) * 256 + t;
        if (i < N_ENT) d_kg_cnt[i] = 0;
        else {
            i -= N_ENT;
            if (i < N_TOT) d_ain_cnt[i] = 0;
        }
        return;
    }
    __shared__ float sU[16][68];
    __shared__ float sI[16][68];
    int ix = bid & 127, iy = bid >> 7;
    int u0 = iy * 16, i0 = ix * 16;
    {
        int ur = uids[u0 + ty];
        *(float4*)&sU[ty][tx * 4] = *(const float4*)(d_sum + (size_t)ur * 64 + tx * 4);
        int ir = iids[i0 + ty];
        *(float4*)&sI[ty][tx * 4] = *(const float4*)(d_sum + (size_t)ir * 64 + tx * 4);
    }
    __syncthreads();
    float acc = 0.f;
    #pragma unroll
    for (int k = 0; k < 64; k++) acc += sU[ty][k] * sI[tx][k];
    out[(size_t)(u0 + ty) * 2048 + i0 + tx] = acc;
}

// ---------------- launch ----------------
extern "C" void kernel_launch(void* const* d_in, const int* in_sizes, int n_in,
                              void* d_out, int out_size) {
    const float* E0   = (const float*)d_in[0];
    const float* rel  = (const float*)d_in[1];
    const float* Wk   = (const float*)d_in[2];
    const float* Wkb  = (const float*)d_in[3];
    const float* Wa   = (const float*)d_in[4];
    const float* Wb   = (const float*)d_in[5];
    const int*   kg_h = (const int*)d_in[6];
    const int*   kg_t = (const int*)d_in[7];
    const int*   kg_r = (const int*)d_in[8];
    const int*   a_r  = (const int*)d_in[9];
    const int*   a_c  = (const int*)d_in[10];
    const float* a_v  = (const float*)d_in[11];
    const int*   uids = (const int*)d_in[12];
    const int*   iids = (const int*)d_in[13];
    float* out = (float*)d_out;

    // 0: hist + init + PQ + zero(rowsum, spine)   [counters zeroed by prev replay's k_final]
    k_setup<<<B_H + B_I + B_P + B_Z, 256>>>(E0, Wk, Wkb, rel, kg_h, a_r);
    // 1: At/Bt + single-pass scans (+cursor init)
    k_atbt_scan<<<B_ATBT + NB_KG + NB_AIN, 1024>>>(E0);
    // 2: scatter with inline logit/exp/rowsum
    k_scatter<<<B_H, 256>>>(kg_h, kg_t, kg_r, a_r, a_c, a_v);

    int cur = 0;
    for (int l = 0; l < 3; l++) {
        // 3,5,7: merged SpMM  (launch index 3 == first SpMM -> ncu profiles it next round)
        k_spmm<<<(N_ENT + N_TOT) / 8, 256>>>(cur);
        // 4,6,8: fusion + users
        k_fusion_users<<<NBF + (N_USR * 16 + 255) / 256, 256>>>(Wa, Wb, cur);
        cur ^= 1;
    }

    // 9: final GEMM + counter re-zero for next replay
    dim3 fb(16, 16);
    k_final<<<8192 + 977, fb>>>(uids, iids, out);
    (void)in_sizes; (void)n_in; (void)out_size;
}

// round 8
// speedup vs baseline: 1.3204x; 1.2166x over previous
#include <cuda_runtime.h>
#include <cuda_fp16.h>
#include <math.h>

#define N_ENT 100000
#define N_USR 50000
#define N_TOT 150000
#define DIM 64
#define E_KG 1500000
#define E_CF 1500000
#define LEAKY 0.01f

#define NB_KG 98    // ceil(100000/1024)
#define NB_AIN 147  // ceil(150000/1024)
#define NBF 1563    // ceil(100000/64)

// k_setup block ranges (256 threads)
#define B_H 11719   // ceil(3,000,000/256) edge hist
#define B_I 9375    // N_TOT*16/256 init float4
#define B_P 9       // PQ + cr
#define B_Z 393     // rowsum + spine zero
// k_atbt_scan (1024 threads)
#define B_ATBT 1563

// ---------------- scratch (static device globals; zero-initialized at load) ----------------
__device__ float d_PQ[128 * 16];
__device__ float d_cr[16];
__device__ float d_At[(size_t)N_ENT * 16];
__device__ float d_Bt[(size_t)N_ENT * 16];
__device__ int   d_kg_cnt[N_ENT];
__device__ int   d_kg_rp[N_ENT + 1];
__device__ int2  d_csr_kg[E_KG];            // (tail*128 byte-offset, exp-logit bits)
__device__ float d_rowsum[N_ENT];
__device__ int   d_ain_cnt[N_TOT];
__device__ int   d_ain_rp[N_TOT + 1];
__device__ int2  d_csr_ain[E_CF];           // (col*128 byte-offset, val bits)
__device__ unsigned d_spine[512];
__device__ __align__(16) __half2 d_kg16[2][(size_t)N_ENT * 32];  // fp16 gather source (kg)
__device__ __align__(16) __half2 d_xy16[2][(size_t)N_TOT * 32];  // fp16 gather source (ain)
__device__ float d_kgA[(size_t)N_ENT * DIM];                     // fp32 spmm_kg out (fusion in)
__device__ float d_ig[(size_t)N_TOT * DIM];
__device__ float d_sum[(size_t)N_TOT * DIM];

// ---------------- f32x2 packed-FMA helpers (sm_103a) ----------------
__device__ __forceinline__ void fma2(unsigned long long& d, unsigned long long a,
                                     unsigned long long b) {
    asm("fma.rn.f32x2 %0, %1, %2, %0;" : "+l"(d) : "l"(a), "l"(b));
}
__device__ __forceinline__ unsigned long long splat2(float x) {
    unsigned long long r;
    asm("mov.b64 %0, {%1, %1};" : "=l"(r) : "r"(__float_as_uint(x)));
    return r;
}
__device__ __forceinline__ void unpack2(unsigned long long v, float& lo, float& hi) {
    unsigned a, b;
    asm("mov.b64 {%0, %1}, %2;" : "=r"(a), "=r"(b) : "l"(v));
    lo = __uint_as_float(a);
    hi = __uint_as_float(b);
}
__device__ __forceinline__ uint2 pack_h4(float a, float b, float c, float d) {
    __half2 h0 = __floats2half2_rn(a, b);
    __half2 h1 = __floats2half2_rn(c, d);
    uint2 u;
    u.x = *(unsigned*)&h0;
    u.y = *(unsigned*)&h1;
    return u;
}

// ================= Launch 0: hist + init copies + PQ/cr + zero rowsum/spine ===============
__global__ void k_setup(const float* __restrict__ E0, const float* __restrict__ Wk,
                        const float* __restrict__ Wkb, const float* __restrict__ rel,
                        const int* __restrict__ kgh, const int* __restrict__ ar) {
    int b = blockIdx.x, tid = threadIdx.x;
    if (b < B_H) {
        int e = b * 256 + tid;
        if (e < E_KG) {
            atomicAdd(&d_kg_cnt[kgh[e]], 1);
        } else {
            e -= E_KG;
            if (e < E_CF) atomicAdd(&d_ain_cnt[ar[e]], 1);
        }
    } else if (b < B_H + B_I) {
        int i = (b - B_H) * 256 + tid;   // exactly N_TOT*16 float4s
        float4 v = ((const float4*)E0)[i];
        ((float4*)d_sum)[i] = v;
        uint2 u = pack_h4(v.x, v.y, v.z, v.w);
        ((uint2*)d_xy16[0])[i] = u;
        if (i < N_ENT * 16) ((uint2*)d_kg16[0])[i] = u;
    } else if (b < B_H + B_I + B_P) {
        int j = (b - B_H - B_I) * 256 + tid;
        if (j < 2048) {
            int jj = j >> 4, r = j & 15;
            float s = 0.f;
            #pragma unroll
            for (int d = 0; d < 64; d++) s += Wk[jj * 64 + d] * rel[r * 64 + d];
            d_PQ[jj * 16 + r] = s;
        } else if (j < 2064) {
            int r = j - 2048;
            float s = 0.f;
            #pragma unroll
            for (int d = 0; d < 64; d++) s += Wkb[d] * rel[r * 64 + d];
            d_cr[r] = s;
        }
    } else {
        int i = (b - B_H - B_I - B_P) * 256 + tid;
        if (i < N_ENT) d_rowsum[i] = 0.f;
        else {
            i -= N_ENT;
            if (i < 512) d_spine[i] = 0u;
        }
    }
}

// ================= Launch 1: At/Bt precompute + single-pass lookback scans ================
__global__ void __launch_bounds__(1024) k_atbt_scan(const float* __restrict__ E0) {
    __shared__ float sm[6144];
    int t = threadIdx.x;
    if (blockIdx.x < B_ATBT) {
        float* sPQ = sm;
        float* sE = sm + 2048;
        int nb = blockIdx.x * 64;
        for (int i = t; i < 2048; i += 1024) sPQ[i] = d_PQ[i];
        for (int i = t; i < 4096; i += 1024) {
            int rr = nb + (i >> 6);
            sE[i] = (rr < N_ENT) ? E0[(size_t)rr * 64 + (i & 63)] : 0.f;
        }
        __syncthreads();
        int ln = t >> 4, r = t & 15;
        float a = 0.f, bb = 0.f;
        #pragma unroll
        for (int j = 0; j < 64; j++) {
            float e = sE[ln * 64 + j];
            a += e * sPQ[j * 16 + r];
            bb += e * sPQ[(64 + j) * 16 + r];
        }
        int n = nb + ln;
        if (n < N_ENT) {
            d_At[(size_t)n * 16 + r] = a;
            d_Bt[(size_t)n * 16 + r] = bb;
        }
        return;
    }
    int b2 = blockIdx.x - B_ATBT;
    int which = (b2 >= NB_KG);
    int b = which ? b2 - NB_KG : b2;
    int* cnt = which ? d_ain_cnt : d_kg_cnt;
    int* rp = which ? d_ain_rp : d_kg_rp;
    int N = which ? N_TOT : N_ENT;
    int base = which ? 256 : 0;
    int* sh = (int*)sm;
    int i = b * 1024 + t;
    int v = (i < N) ? cnt[i] : 0;
    sh[t] = v;
    __syncthreads();
    for (int s = 1; s < 1024; s <<= 1) {
        int x = (t >= s) ? sh[t - s] : 0;
        __syncthreads();
        sh[t] += x;
        __syncthreads();
    }
    int agg = sh[1023];
    __shared__ int s_ex;
    if (t == 0) {
        volatile unsigned* sp = d_spine;
        if (b == 0) {
            __threadfence();
            sp[base] = (2u << 30) | (unsigned)agg;
            s_ex = 0;
        } else {
            __threadfence();
            sp[base + b] = (1u << 30) | (unsigned)agg;
            int ex = 0;
            int p = b - 1;
            while (true) {
                unsigned w;
                do { w = sp[base + p]; } while ((w >> 30) == 0u);
                ex += (int)(w & 0x3FFFFFFFu);
                if ((w >> 30) == 2u) break;
                p--;
            }
            __threadfence();
            sp[base + b] = (2u << 30) | (unsigned)(ex + agg);
            s_ex = ex;
        }
    }
    __syncthreads();
    int ex = s_ex;
    if (i < N) {
        rp[i + 1] = ex + sh[t];
        cnt[i] = ex + sh[t] - v;
    }
    if (b == 0 && t == 0) rp[0] = 0;
}

// ========== Launch 2: merged scatter (kg with inline logit+exp+rowsum; ain plain) ==========
__global__ void k_scatter(const int* __restrict__ h, const int* __restrict__ tt_,
                          const int* __restrict__ r, const int* __restrict__ ar,
                          const int* __restrict__ ac, const float* __restrict__ av) {
    int e = blockIdx.x * blockDim.x + threadIdx.x;
    if (e < E_KG) {
        int hh = h[e], tt = tt_[e], rr = r[e];
        float l = d_At[(size_t)tt * 16 + rr] + d_Bt[(size_t)hh * 16 + rr] + d_cr[rr];
        l = (l >= 0.f) ? l : LEAKY * l;
        float ex = __expf(l);   // logits ~ N(0, 1/8): no max-subtraction needed
        atomicAdd(&d_rowsum[hh], ex);
        int p = atomicAdd(&d_kg_cnt[hh], 1);
        d_csr_kg[p] = make_int2(tt * 128, __float_as_int(ex));
    } else {
        int e2 = e - E_KG;
        if (e2 >= E_CF) return;
        int p = atomicAdd(&d_ain_cnt[ar[e2]], 1);
        d_csr_ain[p] = make_int2(ac[e2] * 128, __float_as_int(av[e2]));
    }
}

// ============ Launches 3,5,7: merged SpMM — 2 rows/warp, fp16 gather, fp32 accum ==========
__global__ void __launch_bounds__(256) k_spmm(int cur) {
    int gw = (blockIdx.x * 256 + threadIdx.x) >> 5;
    int lane = threadIdx.x & 31;
    int l16 = lane & 15;
    int half = lane >> 4;
    const __half2* __restrict__ X16;
    const int2* __restrict__ csr;
    const int* __restrict__ rp;
    int row;
    bool iskg = (gw < N_ENT / 2);
    if (iskg) {
        X16 = d_kg16[cur];
        csr = d_csr_kg;
        rp = d_kg_rp;
        row = gw * 2 + half;
    } else {
        int w = gw - N_ENT / 2;
        X16 = d_xy16[cur];
        csr = d_csr_ain;
        rp = d_ain_rp;
        row = w * 2 + half;
    }
    int s = rp[row], e = rp[row + 1];
    int G = (e - s + 15) >> 4;
    int Gmax = __reduce_max_sync(0xffffffffu, G);
    float ac0 = 0.f, ac1 = 0.f, ac2 = 0.f, ac3 = 0.f;
    const char* Xb = (const char*)X16;
    int loff = l16 * 8;
    for (int g = 0; g < Gmax; g++) {
        int idx = s + g * 16 + l16;
        int off = 0;
        float a = 0.f;
        if (idx < e) {
            int2 ev = csr[idx];
            off = ev.x;
            a = __int_as_float(ev.y);
        }
        int n = e - s - g * 16;
        n = max(0, min(16, n));
        int nr = __reduce_max_sync(0xffffffffu, (n + 3) & ~3);
        for (int j = 0; j < nr; j += 4) {
            int o0 = __shfl_sync(~0u, off, j + 0, 16), o1 = __shfl_sync(~0u, off, j + 1, 16);
            int o2 = __shfl_sync(~0u, off, j + 2, 16), o3 = __shfl_sync(~0u, off, j + 3, 16);
            float a0 = __shfl_sync(~0u, a, j + 0, 16), a1 = __shfl_sync(~0u, a, j + 1, 16);
            float a2 = __shfl_sync(~0u, a, j + 2, 16), a3 = __shfl_sync(~0u, a, j + 3, 16);
            uint2 r0 = *(const uint2*)(Xb + o0 + loff);
            uint2 r1 = *(const uint2*)(Xb + o1 + loff);
            uint2 r2 = *(const uint2*)(Xb + o2 + loff);
            uint2 r3 = *(const uint2*)(Xb + o3 + loff);
            float2 f;
            f = __half22float2(*(__half2*)&r0.x); ac0 += a0 * f.x; ac1 += a0 * f.y;
            f = __half22float2(*(__half2*)&r0.y); ac2 += a0 * f.x; ac3 += a0 * f.y;
            f = __half22float2(*(__half2*)&r1.x); ac0 += a1 * f.x; ac1 += a1 * f.y;
            f = __half22float2(*(__half2*)&r1.y); ac2 += a1 * f.x; ac3 += a1 * f.y;
            f = __half22float2(*(__half2*)&r2.x); ac0 += a2 * f.x; ac1 += a2 * f.y;
            f = __half22float2(*(__half2*)&r2.y); ac2 += a2 * f.x; ac3 += a2 * f.y;
            f = __half22float2(*(__half2*)&r3.x); ac0 += a3 * f.x; ac1 += a3 * f.y;
            f = __half22float2(*(__half2*)&r3.y); ac2 += a3 * f.x; ac3 += a3 * f.y;
        }
    }
    if (iskg) {
        float sc = (e > s) ? 1.f / d_rowsum[row] : 0.f;   // fold softmax normalization
        ac0 *= sc; ac1 *= sc; ac2 *= sc; ac3 *= sc;
        *(float4*)(d_kgA + (size_t)row * 64 + l16 * 4) = make_float4(ac0, ac1, ac2, ac3);
        *(uint2*)((char*)d_kg16[cur ^ 1] + (size_t)row * 128 + loff) =
            pack_h4(ac0, ac1, ac2, ac3);
    } else {
        *(float4*)(d_ig + (size_t)row * 64 + l16 * 4) = make_float4(ac0, ac1, ac2, ac3);
    }
}

// ============ Launches 4,6,8: fusion gate (items, f32x2) + user pass-through ==============
__global__ void k_fusion_users(const float* __restrict__ Wa, const float* __restrict__ Wb,
                               int cur) {
    if (blockIdx.x >= NBF) {
        int i = (blockIdx.x - NBF) * 256 + threadIdx.x;
        if (i >= N_USR * 16) return;
        const float4* src = (const float4*)(d_ig + (size_t)N_ENT * 64);
        float4 v = src[i];
        ((uint2*)(d_xy16[cur ^ 1] + (size_t)N_ENT * 32))[i] = pack_h4(v.x, v.y, v.z, v.w);
        float4* as = (float4*)(d_sum + (size_t)N_ENT * 64);
        float4 a = as[i];
        a.x += v.x; a.y += v.y; a.z += v.z; a.w += v.w;
        as[i] = a;
        return;
    }
    __shared__ float sKG[64][68];
    __shared__ float sIG[64][68];
    const float* __restrict__ KG = d_kgA;
    const float* __restrict__ IG = d_ig;
    int row0 = blockIdx.x * 64;
    int tid = threadIdx.x;  // 256
    for (int i = tid; i < 1024; i += 256) {
        int r = i >> 4, c4 = (i & 15) * 4;
        int gr = row0 + r;
        float4 kgv = make_float4(0.f, 0.f, 0.f, 0.f), igv = kgv;
        if (gr < N_ENT) {
            kgv = *(const float4*)(KG + (size_t)gr * 64 + c4);
            igv = *(const float4*)(IG + (size_t)gr * 64 + c4);
        }
        *(float4*)&sKG[r][c4] = kgv;
        *(float4*)&sIG[r][c4] = igv;
    }
    __syncthreads();
    int tx = tid & 15, ty = tid >> 4;
    unsigned long long acc[4][2];
    #pragma unroll
    for (int i = 0; i < 4; i++) { acc[i][0] = 0ull; acc[i][1] = 0ull; }
    const float4* WaP = (const float4*)(Wa + tx * 4);
    const float4* WbP = (const float4*)(Wb + tx * 4);
    #pragma unroll
    for (int k4 = 0; k4 < 64; k4 += 4) {
        float4 kg[4], ig[4];
        #pragma unroll
        for (int i = 0; i < 4; i++) {
            kg[i] = *(const float4*)&sKG[ty * 4 + i][k4];
            ig[i] = *(const float4*)&sIG[ty * 4 + i][k4];
        }
        #pragma unroll
        for (int kk = 0; kk < 4; kk++) {
            float4 wav = WaP[(k4 + kk) * 16];
            float4 wbv = WbP[(k4 + kk) * 16];
            unsigned long long wa0, wa1, wb0, wb1;
            asm("mov.b64 %0, {%1, %2};" : "=l"(wa0) : "f"(wav.x), "f"(wav.y));
            asm("mov.b64 %0, {%1, %2};" : "=l"(wa1) : "f"(wav.z), "f"(wav.w));
            asm("mov.b64 %0, {%1, %2};" : "=l"(wb0) : "f"(wbv.x), "f"(wbv.y));
            asm("mov.b64 %0, {%1, %2};" : "=l"(wb1) : "f"(wbv.z), "f"(wbv.w));
            #pragma unroll
            for (int i = 0; i < 4; i++) {
                unsigned long long ks = splat2(((const float*)&kg[i])[kk]);
                unsigned long long is2 = splat2(((const float*)&ig[i])[kk]);
                fma2(acc[i][0], ks, wa0);
                fma2(acc[i][1], ks, wa1);
                fma2(acc[i][0], is2, wb0);
                fma2(acc[i][1], is2, wb1);
            }
        }
    }
    #pragma unroll
    for (int i = 0; i < 4; i++) {
        int gr = row0 + ty * 4 + i;
        if (gr >= N_ENT) break;
        float4 kgv = *(const float4*)&sKG[ty * 4 + i][tx * 4];
        float4 igv = *(const float4*)&sIG[ty * 4 + i][tx * 4];
        float s0, s1, s2, s3;
        unpack2(acc[i][0], s0, s1);
        unpack2(acc[i][1], s2, s3);
        float4 o;
        float g;
        g = 1.f / (1.f + __expf(-s0)); o.x = g * kgv.x + (1.f - g) * igv.x;
        g = 1.f / (1.f + __expf(-s1)); o.y = g * kgv.y + (1.f - g) * igv.y;
        g = 1.f / (1.f + __expf(-s2)); o.z = g * kgv.z + (1.f - g) * igv.z;
        g = 1.f / (1.f + __expf(-s3)); o.w = g * kgv.w + (1.f - g) * igv.w;
        *(uint2*)((char*)d_xy16[cur ^ 1] + (size_t)gr * 128 + tx * 8) =
            pack_h4(o.x, o.y, o.z, o.w);
        float4* as = (float4*)(d_sum + (size_t)gr * 64 + tx * 4);
        float4 a = *as;
        a.x += igv.x; a.y += igv.y; a.z += igv.z; a.w += igv.w;
        *as = a;
    }
}

// ====== Launch 9: final score GEMM + re-zero counters for the next graph replay ==========
__global__ void k_final(const int* __restrict__ uids, const int* __restrict__ iids,
                        float* __restrict__ out) {
    int bid = blockIdx.x;
    int tx = threadIdx.x, ty = threadIdx.y;
    if (bid >= 8192) {
        int t = ty * 16 + tx;
        int i = (bid - 8192) * 256 + t;
        if (i < N_ENT) d_kg_cnt[i] = 0;
        else {
            i -= N_ENT;
            if (i < N_TOT) d_ain_cnt[i] = 0;
        }
        return;
    }
    __shared__ float sU[16][68];
    __shared__ float sI[16][68];
    int ix = bid & 127, iy = bid >> 7;
    int u0 = iy * 16, i0 = ix * 16;
    {
        int ur = uids[u0 + ty];
        *(float4*)&sU[ty][tx * 4] = *(const float4*)(d_sum + (size_t)ur * 64 + tx * 4);
        int ir = iids[i0 + ty];
        *(float4*)&sI[ty][tx * 4] = *(const float4*)(d_sum + (size_t)ir * 64 + tx * 4);
    }
    __syncthreads();
    float acc = 0.f;
    #pragma unroll
    for (int k = 0; k < 64; k++) acc += sU[ty][k] * sI[tx][k];
    out[(size_t)(u0 + ty) * 2048 + i0 + tx] = acc;
}

// ---------------- launch ----------------
extern "C" void kernel_launch(void* const* d_in, const int* in_sizes, int n_in,
                              void* d_out, int out_size) {
    const float* E0   = (const float*)d_in[0];
    const float* rel  = (const float*)d_in[1];
    const float* Wk   = (const float*)d_in[2];
    const float* Wkb  = (const float*)d_in[3];
    const float* Wa   = (const float*)d_in[4];
    const float* Wb   = (const float*)d_in[5];
    const int*   kg_h = (const int*)d_in[6];
    const int*   kg_t = (const int*)d_in[7];
    const int*   kg_r = (const int*)d_in[8];
    const int*   a_r  = (const int*)d_in[9];
    const int*   a_c  = (const int*)d_in[10];
    const float* a_v  = (const float*)d_in[11];
    const int*   uids = (const int*)d_in[12];
    const int*   iids = (const int*)d_in[13];
    float* out = (float*)d_out;

    k_setup<<<B_H + B_I + B_P + B_Z, 256>>>(E0, Wk, Wkb, rel, kg_h, a_r);
    k_atbt_scan<<<B_ATBT + NB_KG + NB_AIN, 1024>>>(E0);
    k_scatter<<<B_H, 256>>>(kg_h, kg_t, kg_r, a_r, a_c, a_v);

    int cur = 0;
    for (int l = 0; l < 3; l++) {
        // 125,000 warps: 2 rows per warp over 250,000 total rows
        k_spmm<<<15625, 256>>>(cur);
        k_fusion_users<<<NBF + (N_USR * 16 + 255) / 256, 256>>>(Wa, Wb, cur);
        cur ^= 1;
    }

    dim3 fb(16, 16);
    k_final<<<8192 + 977, fb>>>(uids, iids, out);
    (void)in_sizes; (void)n_in; (void)out_size;
}

// round 9
// speedup vs baseline: 1.4209x; 1.0762x over previous
#include <cuda_runtime.h>
#include <cuda_fp16.h>
#include <math.h>

#define N_ENT 100000
#define N_USR 50000
#define N_TOT 150000
#define DIM 64
#define E_KG 1500000
#define E_CF 1500000
#define LEAKY 0.01f

#define NB_KG 98    // ceil(100000/1024)
#define NB_AIN 147  // ceil(150000/1024)
#define NBF 1563    // ceil(100000/64)

#define B_H 11719   // ceil(3,000,000/256) edge hist
#define B_I 9375    // N_TOT*16/256 init float4
#define B_P 9       // PQ + cr
#define B_Z 393     // rowsum + spine zero
#define B_ATBT 1563

// ---------------- scratch (static device globals; zero-initialized at load) ----------------
__device__ float d_PQ[128 * 16];
__device__ float d_cr[16];
__device__ float d_At[(size_t)N_ENT * 16];
__device__ float d_Bt[(size_t)N_ENT * 16];
__device__ int   d_kg_cnt[N_ENT];
__device__ int   d_kg_rp[N_ENT + 1];
__device__ int2  d_csr_kg[E_KG];            // (tail*128 byte-offset, half2(a,a) bits)
__device__ float d_rowsum[N_ENT];
__device__ int   d_ain_cnt[N_TOT];
__device__ int   d_ain_rp[N_TOT + 1];
__device__ int2  d_csr_ain[E_CF];           // (col*128 byte-offset, half2(v,v) bits)
__device__ unsigned d_spine[512];
__device__ __align__(16) __half2 d_kg16[2][(size_t)N_ENT * 32];  // fp16 gather source (kg)
__device__ __align__(16) __half2 d_xy16[2][(size_t)N_TOT * 32];  // fp16 gather source (ain)
__device__ float d_ig[(size_t)N_TOT * DIM];                      // fp32 ain-spmm out
__device__ float d_sum[(size_t)N_TOT * DIM];

// ---------------- helpers ----------------
__device__ __forceinline__ void fma2(unsigned long long& d, unsigned long long a,
                                     unsigned long long b) {
    asm("fma.rn.f32x2 %0, %1, %2, %0;" : "+l"(d) : "l"(a), "l"(b));
}
__device__ __forceinline__ unsigned long long splat2(float x) {
    unsigned long long r;
    asm("mov.b64 %0, {%1, %1};" : "=l"(r) : "r"(__float_as_uint(x)));
    return r;
}
__device__ __forceinline__ void unpack2(unsigned long long v, float& lo, float& hi) {
    unsigned a, b;
    asm("mov.b64 {%0, %1}, %2;" : "=r"(a), "=r"(b) : "l"(v));
    lo = __uint_as_float(a);
    hi = __uint_as_float(b);
}
__device__ __forceinline__ uint2 pack_h4(float a, float b, float c, float d) {
    __half2 h0 = __floats2half2_rn(a, b);
    __half2 h1 = __floats2half2_rn(c, d);
    uint2 u;
    u.x = *(unsigned*)&h0;
    u.y = *(unsigned*)&h1;
    return u;
}
__device__ __forceinline__ __half2 u2h(unsigned u) { return *(__half2*)&u; }
__device__ __forceinline__ unsigned h2u(__half2 h) { return *(unsigned*)&h; }

// ================= Launch 0: edge histograms ===============
__global__ void k_hist(const int* __restrict__ kgh, const int* __restrict__ ar) {
    int e = blockIdx.x * 256 + threadIdx.x;
    if (e < E_KG) {
        atomicAdd(&d_kg_cnt[kgh[e]], 1);
    } else {
        e -= E_KG;
        if (e < E_CF) atomicAdd(&d_ain_cnt[ar[e]], 1);
    }
}

// ================= Launch 1: init copies + PQ/cr + zero rowsum/spine ===============
__global__ void k_setup2(const float* __restrict__ E0, const float* __restrict__ Wk,
                         const float* __restrict__ Wkb, const float* __restrict__ rel) {
    int b = blockIdx.x, tid = threadIdx.x;
    if (b < B_I) {
        int i = b * 256 + tid;   // exactly N_TOT*16 float4s
        float4 v = ((const float4*)E0)[i];
        ((float4*)d_sum)[i] = v;
        uint2 u = pack_h4(v.x, v.y, v.z, v.w);
        ((uint2*)d_xy16[0])[i] = u;
        if (i < N_ENT * 16) ((uint2*)d_kg16[0])[i] = u;
    } else if (b < B_I + B_P) {
        int j = (b - B_I) * 256 + tid;
        if (j < 2048) {
            int jj = j >> 4, r = j & 15;
            float s = 0.f;
            #pragma unroll
            for (int d = 0; d < 64; d++) s += Wk[jj * 64 + d] * rel[r * 64 + d];
            d_PQ[jj * 16 + r] = s;
        } else if (j < 2064) {
            int r = j - 2048;
            float s = 0.f;
            #pragma unroll
            for (int d = 0; d < 64; d++) s += Wkb[d] * rel[r * 64 + d];
            d_cr[r] = s;
        }
    } else {
        int i = (b - B_I - B_P) * 256 + tid;
        if (i < N_ENT) d_rowsum[i] = 0.f;
        else {
            i -= N_ENT;
            if (i < 512) d_spine[i] = 0u;
        }
    }
}

// ================= Launch 2: At/Bt precompute + single-pass lookback scans ================
__global__ void __launch_bounds__(1024) k_atbt_scan(const float* __restrict__ E0) {
    __shared__ float sm[6144];
    int t = threadIdx.x;
    if (blockIdx.x < B_ATBT) {
        float* sPQ = sm;
        float* sE = sm + 2048;
        int nb = blockIdx.x * 64;
        for (int i = t; i < 2048; i += 1024) sPQ[i] = d_PQ[i];
        for (int i = t; i < 4096; i += 1024) {
            int rr = nb + (i >> 6);
            sE[i] = (rr < N_ENT) ? E0[(size_t)rr * 64 + (i & 63)] : 0.f;
        }
        __syncthreads();
        int ln = t >> 4, r = t & 15;
        float a = 0.f, bb = 0.f;
        #pragma unroll
        for (int j = 0; j < 64; j++) {
            float e = sE[ln * 64 + j];
            a += e * sPQ[j * 16 + r];
            bb += e * sPQ[(64 + j) * 16 + r];
        }
        int n = nb + ln;
        if (n < N_ENT) {
            d_At[(size_t)n * 16 + r] = a;
            d_Bt[(size_t)n * 16 + r] = bb;
        }
        return;
    }
    int b2 = blockIdx.x - B_ATBT;
    int which = (b2 >= NB_KG);
    int b = which ? b2 - NB_KG : b2;
    int* cnt = which ? d_ain_cnt : d_kg_cnt;
    int* rp = which ? d_ain_rp : d_kg_rp;
    int N = which ? N_TOT : N_ENT;
    int base = which ? 256 : 0;
    int* sh = (int*)sm;
    int i = b * 1024 + t;
    int v = (i < N) ? cnt[i] : 0;
    sh[t] = v;
    __syncthreads();
    for (int s = 1; s < 1024; s <<= 1) {
        int x = (t >= s) ? sh[t - s] : 0;
        __syncthreads();
        sh[t] += x;
        __syncthreads();
    }
    int agg = sh[1023];
    __shared__ int s_ex;
    if (t == 0) {
        volatile unsigned* sp = d_spine;
        if (b == 0) {
            __threadfence();
            sp[base] = (2u << 30) | (unsigned)agg;
            s_ex = 0;
        } else {
            __threadfence();
            sp[base + b] = (1u << 30) | (unsigned)agg;
            int ex = 0;
            int p = b - 1;
            while (true) {
                unsigned w;
                do { w = sp[base + p]; } while ((w >> 30) == 0u);
                ex += (int)(w & 0x3FFFFFFFu);
                if ((w >> 30) == 2u) break;
                p--;
            }
            __threadfence();
            sp[base + b] = (2u << 30) | (unsigned)(ex + agg);
            s_ex = ex;
        }
    }
    __syncthreads();
    int ex = s_ex;
    if (i < N) {
        rp[i + 1] = ex + sh[t];
        cnt[i] = ex + sh[t] - v;
    }
    if (b == 0 && t == 0) rp[0] = 0;
}

// ========== Launch 3: merged scatter (kg: inline logit+exp+rowsum; ain plain) ==========
__global__ void k_scatter(const int* __restrict__ h, const int* __restrict__ tt_,
                          const int* __restrict__ r, const int* __restrict__ ar,
                          const int* __restrict__ ac, const float* __restrict__ av) {
    int e = blockIdx.x * blockDim.x + threadIdx.x;
    if (e < E_KG) {
        int hh = h[e], tt = tt_[e], rr = r[e];
        float l = d_At[(size_t)tt * 16 + rr] + d_Bt[(size_t)hh * 16 + rr] + d_cr[rr];
        l = (l >= 0.f) ? l : LEAKY * l;
        float ex = __expf(l);   // logits ~ N(0, 1/8): no max-subtraction needed
        atomicAdd(&d_rowsum[hh], ex);
        int p = atomicAdd(&d_kg_cnt[hh], 1);
        d_csr_kg[p] = make_int2(tt * 128, (int)h2u(__float2half2_rn(ex)));
    } else {
        int e2 = e - E_KG;
        if (e2 >= E_CF) return;
        int p = atomicAdd(&d_ain_cnt[ar[e2]], 1);
        d_csr_ain[p] = make_int2(ac[e2] * 128, (int)h2u(__float2half2_rn(av[e2])));
    }
}

// ===== Launches 4,6,8: merged SpMM — 2 rows/warp, fp16 gather, HFMA2 + group flush =====
__global__ void __launch_bounds__(256) k_spmm(int cur) {
    int gw = (blockIdx.x * 256 + threadIdx.x) >> 5;
    int lane = threadIdx.x & 31;
    int l16 = lane & 15;
    int half = lane >> 4;
    const __half2* __restrict__ X16;
    const int2* __restrict__ csr;
    const int* __restrict__ rp;
    int row;
    bool iskg = (gw < N_ENT / 2);
    if (iskg) {
        X16 = d_kg16[cur];
        csr = d_csr_kg;
        rp = d_kg_rp;
        row = gw * 2 + half;
    } else {
        int w = gw - N_ENT / 2;
        X16 = d_xy16[cur];
        csr = d_csr_ain;
        rp = d_ain_rp;
        row = w * 2 + half;
    }
    int s = rp[row], e = rp[row + 1];
    int G = (e - s + 15) >> 4;
    int Gmax = __reduce_max_sync(0xffffffffu, G);
    float ac0 = 0.f, ac1 = 0.f, ac2 = 0.f, ac3 = 0.f;
    const char* Xb = (const char*)X16;
    int loff = l16 * 8;
    const __half2 hz = __floats2half2_rn(0.f, 0.f);
    for (int g = 0; g < Gmax; g++) {
        int idx = s + g * 16 + l16;
        int off = 0;
        unsigned ab = 0;      // half2(0,0)
        if (idx < e) {
            int2 ev = csr[idx];
            off = ev.x;
            ab = (unsigned)ev.y;
        }
        int n = e - s - g * 16;
        n = max(0, min(16, n));
        int nr = __reduce_max_sync(0xffffffffu, (n + 3) & ~3);
        __half2 h0 = hz, h1 = hz, h2 = hz, h3 = hz;
        for (int j = 0; j < nr; j += 4) {
            int o0 = __shfl_sync(~0u, off, j + 0, 16), o1 = __shfl_sync(~0u, off, j + 1, 16);
            int o2 = __shfl_sync(~0u, off, j + 2, 16), o3 = __shfl_sync(~0u, off, j + 3, 16);
            unsigned b0 = __shfl_sync(~0u, ab, j + 0, 16), b1 = __shfl_sync(~0u, ab, j + 1, 16);
            unsigned b2 = __shfl_sync(~0u, ab, j + 2, 16), b3 = __shfl_sync(~0u, ab, j + 3, 16);
            uint2 r0 = *(const uint2*)(Xb + o0 + loff);
            uint2 r1 = *(const uint2*)(Xb + o1 + loff);
            uint2 r2 = *(const uint2*)(Xb + o2 + loff);
            uint2 r3 = *(const uint2*)(Xb + o3 + loff);
            h0 = __hfma2(u2h(b0), u2h(r0.x), h0);
            h1 = __hfma2(u2h(b0), u2h(r0.y), h1);
            h2 = __hfma2(u2h(b1), u2h(r1.x), h2);
            h3 = __hfma2(u2h(b1), u2h(r1.y), h3);
            h0 = __hfma2(u2h(b2), u2h(r2.x), h0);
            h1 = __hfma2(u2h(b2), u2h(r2.y), h1);
            h2 = __hfma2(u2h(b3), u2h(r3.x), h2);
            h3 = __hfma2(u2h(b3), u2h(r3.y), h3);
        }
        // flush half partials (<=8-term chains) into fp32 accumulators
        float2 f0 = __half22float2(h0), f1 = __half22float2(h1);
        float2 f2 = __half22float2(h2), f3 = __half22float2(h3);
        ac0 += f0.x + f2.x;
        ac1 += f0.y + f2.y;
        ac2 += f1.x + f3.x;
        ac3 += f1.y + f3.y;
    }
    if (iskg) {
        float sc = (e > s) ? 1.f / d_rowsum[row] : 0.f;   // fold softmax normalization
        ac0 *= sc; ac1 *= sc; ac2 *= sc; ac3 *= sc;
        *(uint2*)((char*)d_kg16[cur ^ 1] + (size_t)row * 128 + loff) =
            pack_h4(ac0, ac1, ac2, ac3);
    } else {
        *(float4*)(d_ig + (size_t)row * 64 + l16 * 4) = make_float4(ac0, ac1, ac2, ac3);
    }
}

// ===== Launches 5,7,9: fusion gate (items, f32x2) + user pass-through =====
__global__ void k_fusion_users(const float* __restrict__ Wa, const float* __restrict__ Wb,
                               int cur) {
    if (blockIdx.x >= NBF) {
        int i = (blockIdx.x - NBF) * 256 + threadIdx.x;
        if (i >= N_USR * 16) return;
        const float4* src = (const float4*)(d_ig + (size_t)N_ENT * 64);
        float4 v = src[i];
        ((uint2*)(d_xy16[cur ^ 1] + (size_t)N_ENT * 32))[i] = pack_h4(v.x, v.y, v.z, v.w);
        float4* as = (float4*)(d_sum + (size_t)N_ENT * 64);
        float4 a = as[i];
        a.x += v.x; a.y += v.y; a.z += v.z; a.w += v.w;
        as[i] = a;
        return;
    }
    __shared__ float sKG[64][68];
    __shared__ float sIG[64][68];
    const char* __restrict__ KG16 = (const char*)d_kg16[cur ^ 1];
    const float* __restrict__ IG = d_ig;
    int row0 = blockIdx.x * 64;
    int tid = threadIdx.x;  // 256
    for (int i = tid; i < 1024; i += 256) {
        int r = i >> 4, c4 = (i & 15) * 4;
        int gr = row0 + r;
        float4 kgv = make_float4(0.f, 0.f, 0.f, 0.f), igv = kgv;
        if (gr < N_ENT) {
            uint2 u = *(const uint2*)(KG16 + (size_t)gr * 128 + (i & 15) * 8);
            float2 fa = __half22float2(u2h(u.x)), fb = __half22float2(u2h(u.y));
            kgv = make_float4(fa.x, fa.y, fb.x, fb.y);
            igv = *(const float4*)(IG + (size_t)gr * 64 + c4);
        }
        *(float4*)&sKG[r][c4] = kgv;
        *(float4*)&sIG[r][c4] = igv;
    }
    __syncthreads();
    int tx = tid & 15, ty = tid >> 4;
    unsigned long long acc[4][2];
    #pragma unroll
    for (int i = 0; i < 4; i++) { acc[i][0] = 0ull; acc[i][1] = 0ull; }
    const float4* WaP = (const float4*)(Wa + tx * 4);
    const float4* WbP = (const float4*)(Wb + tx * 4);
    #pragma unroll
    for (int k4 = 0; k4 < 64; k4 += 4) {
        float4 kg[4], ig[4];
        #pragma unroll
        for (int i = 0; i < 4; i++) {
            kg[i] = *(const float4*)&sKG[ty * 4 + i][k4];
            ig[i] = *(const float4*)&sIG[ty * 4 + i][k4];
        }
        #pragma unroll
        for (int kk = 0; kk < 4; kk++) {
            float4 wav = WaP[(k4 + kk) * 16];
            float4 wbv = WbP[(k4 + kk) * 16];
            unsigned long long wa0, wa1, wb0, wb1;
            asm("mov.b64 %0, {%1, %2};" : "=l"(wa0) : "f"(wav.x), "f"(wav.y));
            asm("mov.b64 %0, {%1, %2};" : "=l"(wa1) : "f"(wav.z), "f"(wav.w));
            asm("mov.b64 %0, {%1, %2};" : "=l"(wb0) : "f"(wbv.x), "f"(wbv.y));
            asm("mov.b64 %0, {%1, %2};" : "=l"(wb1) : "f"(wbv.z), "f"(wbv.w));
            #pragma unroll
            for (int i = 0; i < 4; i++) {
                unsigned long long ks = splat2(((const float*)&kg[i])[kk]);
                unsigned long long is2 = splat2(((const float*)&ig[i])[kk]);
                fma2(acc[i][0], ks, wa0);
                fma2(acc[i][1], ks, wa1);
                fma2(acc[i][0], is2, wb0);
                fma2(acc[i][1], is2, wb1);
            }
        }
    }
    #pragma unroll
    for (int i = 0; i < 4; i++) {
        int gr = row0 + ty * 4 + i;
        if (gr >= N_ENT) break;
        float4 kgv = *(const float4*)&sKG[ty * 4 + i][tx * 4];
        float4 igv = *(const float4*)&sIG[ty * 4 + i][tx * 4];
        float s0, s1, s2, s3;
        unpack2(acc[i][0], s0, s1);
        unpack2(acc[i][1], s2, s3);
        float4 o;
        float g;
        g = 1.f / (1.f + __expf(-s0)); o.x = g * kgv.x + (1.f - g) * igv.x;
        g = 1.f / (1.f + __expf(-s1)); o.y = g * kgv.y + (1.f - g) * igv.y;
        g = 1.f / (1.f + __expf(-s2)); o.z = g * kgv.z + (1.f - g) * igv.z;
        g = 1.f / (1.f + __expf(-s3)); o.w = g * kgv.w + (1.f - g) * igv.w;
        *(uint2*)((char*)d_xy16[cur ^ 1] + (size_t)gr * 128 + tx * 8) =
            pack_h4(o.x, o.y, o.z, o.w);
        float4* as = (float4*)(d_sum + (size_t)gr * 64 + tx * 4);
        float4 a = *as;
        a.x += igv.x; a.y += igv.y; a.z += igv.z; a.w += igv.w;
        *as = a;
    }
}

// ====== Launch 10: final score GEMM + re-zero counters for the next graph replay ==========
__global__ void k_final(const int* __restrict__ uids, const int* __restrict__ iids,
                        float* __restrict__ out) {
    int bid = blockIdx.x;
    int tx = threadIdx.x, ty = threadIdx.y;
    if (bid >= 8192) {
        int t = ty * 16 + tx;
        int i = (bid - 8192) * 256 + t;
        if (i < N_ENT) d_kg_cnt[i] = 0;
        else {
            i -= N_ENT;
            if (i < N_TOT) d_ain_cnt[i] = 0;
        }
        return;
    }
    __shared__ float sU[16][68];
    __shared__ float sI[16][68];
    int ix = bid & 127, iy = bid >> 7;
    int u0 = iy * 16, i0 = ix * 16;
    {
        int ur = uids[u0 + ty];
        *(float4*)&sU[ty][tx * 4] = *(const float4*)(d_sum + (size_t)ur * 64 + tx * 4);
        int ir = iids[i0 + ty];
        *(float4*)&sI[ty][tx * 4] = *(const float4*)(d_sum + (size_t)ir * 64 + tx * 4);
    }
    __syncthreads();
    float acc = 0.f;
    #pragma unroll
    for (int k = 0; k < 64; k++) acc += sU[ty][k] * sI[tx][k];
    out[(size_t)(u0 + ty) * 2048 + i0 + tx] = acc;
}

// ---------------- launch ----------------
extern "C" void kernel_launch(void* const* d_in, const int* in_sizes, int n_in,
                              void* d_out, int out_size) {
    const float* E0   = (const float*)d_in[0];
    const float* rel  = (const float*)d_in[1];
    const float* Wk   = (const float*)d_in[2];
    const float* Wkb  = (const float*)d_in[3];
    const float* Wa   = (const float*)d_in[4];
    const float* Wb   = (const float*)d_in[5];
    const int*   kg_h = (const int*)d_in[6];
    const int*   kg_t = (const int*)d_in[7];
    const int*   kg_r = (const int*)d_in[8];
    const int*   a_r  = (const int*)d_in[9];
    const int*   a_c  = (const int*)d_in[10];
    const float* a_v  = (const float*)d_in[11];
    const int*   uids = (const int*)d_in[12];
    const int*   iids = (const int*)d_in[13];
    float* out = (float*)d_out;

    // 0: hist   1: init+PQ+zero   2: atbt+scan   3: scatter
    k_hist<<<B_H, 256>>>(kg_h, a_r);
    k_setup2<<<B_I + B_P + B_Z, 256>>>(E0, Wk, Wkb, rel);
    k_atbt_scan<<<B_ATBT + NB_KG + NB_AIN, 1024>>>(E0);
    k_scatter<<<B_H, 256>>>(kg_h, kg_t, kg_r, a_r, a_c, a_v);

    int cur = 0;
    for (int l = 0; l < 3; l++) {
        // 4,6,8: spmm     5,7,9: fusion  (launch idx 5 -> ncu profiles fusion next round)
        k_spmm<<<15625, 256>>>(cur);
        k_fusion_users<<<NBF + (N_USR * 16 + 255) / 256, 256>>>(Wa, Wb, cur);
        cur ^= 1;
    }

    dim3 fb(16, 16);
    k_final<<<8192 + 977, fb>>>(uids, iids, out);
    (void)in_sizes; (void)n_in; (void)out_size;
}